// round 17
// baseline (speedup 1.0000x reference)
#include <cuda_runtime.h>
#include <cuda_fp16.h>
#include <cstdint>

#define TT 2048
#define DD 1024
#define HH 16
#define HSZ 64
#define DFF 4096

// ---------------- scratch (no allocs allowed) ----------------
__device__ __half g_h[TT * DD];            // LN output (fp16)
__device__ __half g_wqkvT[3 * DD * DD];    // QKV weights, [3D][D] K-major (fp16)
__device__ __half g_WoT[DD * DD];          // Wo^T (fp16)
__device__ __half g_W1T[DD * DFF];         // W1^T (fp16)
__device__ __half g_W2T[DFF * DD];         // W2^T (fp16)
__device__ __half g_qkv[TT * 3 * DD];      // QKV activations (fp16)
__device__ __half g_att[TT * DD];          // attention output (fp16)
__device__ float  g_x2[TT * DD];           // residual after attention (fp32)
__device__ __half g_ff[TT * DFF];          // FFN hidden (fp16)
__device__ float  g_pO[16 * 16 * 2 * 64 * 64];   // split-K partials
__device__ float  g_pml[16 * 16 * 2 * 64 * 2];   // raw (m, l)
__device__ int    g_cnt[256];                    // split-K tickets

// ---------------- helpers ----------------
__device__ __forceinline__ uint32_t smem_u32(const void* p) {
    return (uint32_t)__cvta_generic_to_shared(p);
}
__device__ __forceinline__ uint32_t swz(uint32_t off) {
    return off ^ ((off >> 3) & 0x70);
}
__device__ __forceinline__ void mma_f16(
    float& d0, float& d1, float& d2, float& d3,
    uint32_t a0, uint32_t a1, uint32_t a2, uint32_t a3,
    uint32_t b0, uint32_t b1)
{
    asm volatile(
        "mma.sync.aligned.m16n8k16.row.col.f32.f16.f16.f32 "
        "{%0,%1,%2,%3}, {%4,%5,%6,%7}, {%8,%9}, {%0,%1,%2,%3};\n"
        : "+f"(d0), "+f"(d1), "+f"(d2), "+f"(d3)
        : "r"(a0), "r"(a1), "r"(a2), "r"(a3), "r"(b0), "r"(b1));
}
__device__ __forceinline__ void ldmx4(
    uint32_t& r0, uint32_t& r1, uint32_t& r2, uint32_t& r3, uint32_t addr)
{
    asm volatile("ldmatrix.sync.aligned.m8n8.x4.shared.b16 {%0,%1,%2,%3}, [%4];"
                 : "=r"(r0), "=r"(r1), "=r"(r2), "=r"(r3) : "r"(addr) : "memory");
}
__device__ __forceinline__ void ldmx4t(
    uint32_t& r0, uint32_t& r1, uint32_t& r2, uint32_t& r3, uint32_t addr)
{
    asm volatile("ldmatrix.sync.aligned.m8n8.x4.trans.shared.b16 {%0,%1,%2,%3}, [%4];"
                 : "=r"(r0), "=r"(r1), "=r"(r2), "=r"(r3) : "r"(addr) : "memory");
}
__device__ __forceinline__ void cpasync16(uint32_t saddr, const void* gaddr) {
    asm volatile("cp.async.cg.shared.global [%0], [%1], 16;" :: "r"(saddr), "l"(gaddr));
}
__device__ __forceinline__ uint32_t packh2(float lo, float hi) {
    __half2 h = __floats2half2_rn(lo, hi);
    return *reinterpret_cast<uint32_t*>(&h);
}
#define CP_COMMIT() asm volatile("cp.async.commit_group;" ::: "memory")
#define CP_WAIT(n)  asm volatile("cp.async.wait_group %0;" :: "n"(n) : "memory")

// ---------------- fast exp2 (fma pipe) ----------------
__device__ __forceinline__ float fexp2(float x) {
    x = fmaxf(x, -120.f);
    float k  = __fadd_rn(x, 12582912.f);
    int   sc = __float_as_int(k) << 23;
    float f  = __fsub_rn(x, __fsub_rn(k, 12582912.f));
    float p  = 0.0013333558f;
    p = fmaf(p, f, 0.0096181291f);
    p = fmaf(p, f, 0.0555041087f);
    p = fmaf(p, f, 0.2402265070f);
    p = fmaf(p, f, 0.6931471806f);
    p = fmaf(p, f, 1.0f);
    return __int_as_float(__float_as_int(p) + sc);
}

// ---------------- LayerNorm row (device fn, emits fp16) ----------------
__device__ __forceinline__ void ln_row(
    const float* __restrict__ x, const float* __restrict__ g,
    const float* __restrict__ b, __half* __restrict__ y, int row, int tid)
{
    float4 v = reinterpret_cast<const float4*>(x + (size_t)row * DD)[tid];
    float s  = v.x + v.y + v.z + v.w;
    float ss = v.x * v.x + v.y * v.y + v.z * v.z + v.w * v.w;
    #pragma unroll
    for (int o = 16; o > 0; o >>= 1) {
        s  += __shfl_xor_sync(0xffffffffu, s, o);
        ss += __shfl_xor_sync(0xffffffffu, ss, o);
    }
    __shared__ float sb[8], ssb[8], stats[2];
    int wid = tid >> 5, lane = tid & 31;
    if (lane == 0) { sb[wid] = s; ssb[wid] = ss; }
    __syncthreads();
    if (tid == 0) {
        float a = 0.f, c = 0.f;
        #pragma unroll
        for (int i = 0; i < 8; i++) { a += sb[i]; c += ssb[i]; }
        float mean = a * (1.0f / DD);
        float var  = c * (1.0f / DD) - mean * mean;
        stats[0] = mean;
        stats[1] = rsqrtf(var + 1e-6f);
    }
    __syncthreads();
    float mean = stats[0], rstd = stats[1];
    float4 gg = reinterpret_cast<const float4*>(g)[tid];
    float4 bb = reinterpret_cast<const float4*>(b)[tid];
    union { __half2 h[2]; uint2 u; } pk;
    pk.h[0] = __floats2half2_rn((v.x - mean) * rstd * gg.x + bb.x,
                                (v.y - mean) * rstd * gg.y + bb.y);
    pk.h[1] = __floats2half2_rn((v.z - mean) * rstd * gg.z + bb.z,
                                (v.w - mean) * rstd * gg.w + bb.w);
    reinterpret_cast<uint2*>(y + (size_t)row * DD)[tid] = pk.u;
}

__global__ __launch_bounds__(256) void ln_kernel(
    const float* __restrict__ x, const float* __restrict__ g,
    const float* __restrict__ b, __half* __restrict__ y)
{
    ln_row(x, g, b, y, blockIdx.x, threadIdx.x);
}

// ---------------- prep: transposes + LN1 + ticket zeroing in ONE launch ----------------
// [0,12288): transposes.  [12288, 14336): LN1 rows.  14336: zero tickets.
__global__ __launch_bounds__(256) void prep_kernel(
    const float* __restrict__ Wq, const float* __restrict__ Wk,
    const float* __restrict__ Wv, const float* __restrict__ Wo,
    const float* __restrict__ W1, const float* __restrict__ W2,
    __half* __restrict__ wqkvT, __half* __restrict__ woT,
    __half* __restrict__ w1T, __half* __restrict__ w2T,
    const float* __restrict__ x, const float* __restrict__ ln1s,
    const float* __restrict__ ln1b, __half* __restrict__ hout,
    int* __restrict__ cnt)
{
    const int b = blockIdx.x;
    if (b >= 14336) {
        if (threadIdx.x < 256) cnt[threadIdx.x] = 0;
        return;
    }
    if (b >= 12288) {
        ln_row(x, ln1s, ln1b, hout, b - 12288, threadIdx.x);
        return;
    }
    __shared__ float t[32][33];
    const float* ip; __half* op;
    int R, C, bx, by;
    if (b < 3072) {
        const int w = b >> 10;
        const int r = b & 1023;
        const int head = r >> 6;
        const int rr = r & 63;
        bx = (rr & 1) * 32;
        by = (rr >> 1) * 32;
        ip = (w == 0 ? Wq : (w == 1 ? Wk : Wv)) + (size_t)head * DD * HSZ;
        op = wqkvT + (size_t)w * DD * DD + (size_t)head * HSZ * DD;
        R = DD; C = HSZ;
    } else if (b < 4096) {
        const int r = b - 3072;
        bx = (r & 31) * 32; by = (r >> 5) * 32;
        ip = Wo; op = woT; R = DD; C = DD;
    } else if (b < 8192) {
        const int r = b - 4096;
        bx = (r & 127) * 32; by = (r >> 7) * 32;
        ip = W1; op = w1T; R = DD; C = DFF;
    } else {
        const int r = b - 8192;
        bx = (r & 31) * 32; by = (r >> 5) * 32;
        ip = W2; op = w2T; R = DFF; C = DD;
    }
    const int x_ = threadIdx.x & 31, y_ = threadIdx.x >> 5;
    #pragma unroll
    for (int j = 0; j < 32; j += 8)
        t[y_ + j][x_] = ip[(size_t)(by + y_ + j) * C + bx + x_];
    __syncthreads();
    #pragma unroll
    for (int j = 0; j < 32; j += 8)
        op[(size_t)(bx + y_ + j) * R + by + x_] = __float2half_rn(t[x_][y_ + j]);
}

// ---------------- fp16 mma.sync GEMM (frozen) ----------------
#define TG_STAGE 32768
#define TG_SMEM  (3 * TG_STAGE)

template <int EPI>
__global__ __launch_bounds__(256, 1) void tg2(
    int M, int N, int K,
    const __half* __restrict__ A, const __half* __restrict__ Bt,
    const float* __restrict__ bias, const float* __restrict__ resid,
    void* __restrict__ Cv)
{
    extern __shared__ float dynsm[];
    const int tid  = threadIdx.x;
    const int warp = tid >> 5, lane = tid & 31;
    const int wm = warp & 1, wn = warp >> 1;
    const int g = lane >> 2, tg = lane & 3;
    const int brow = blockIdx.y, bcol = blockIdx.x;

    const uint32_t sbase = smem_u32(dynsm);
    const int r0 = tid >> 3;
    const int ck = tid & 7;
    const __half* Ab = A  + (size_t)(brow * 128) * K + ck * 8;
    const __half* Bb = Bt + (size_t)(bcol * 128) * K + ck * 8;
    const int KT = K >> 6;

    const int aRow = (lane & 7) + ((lane >> 3) & 1) * 8;
    const int aChk = (lane >> 4);
    const int bRow = (lane & 7) + (lane >> 4) * 8;
    const int bChk = (lane >> 3) & 1;

    float acc[4][4][4];
    #pragma unroll
    for (int mt = 0; mt < 4; mt++)
        #pragma unroll
        for (int nt = 0; nt < 4; nt++)
            #pragma unroll
            for (int i = 0; i < 4; i++) acc[mt][nt][i] = 0.f;

    auto load_stage = [&](int kt, int s) {
        const uint32_t sA = sbase + s * TG_STAGE;
        const uint32_t sB = sA + 16384;
        const int k0 = kt * 64;
        #pragma unroll
        for (int j = 0; j < 4; ++j) {
            const int r = j * 32 + r0;
            const uint32_t off = swz((uint32_t)(r * 128 + ck * 16));
            cpasync16(sA + off, Ab + (size_t)r * K + k0);
            cpasync16(sB + off, Bb + (size_t)r * K + k0);
        }
        CP_COMMIT();
    };

    load_stage(0, 0);
    if (KT > 1) load_stage(1, 1);

    for (int kt = 0; kt < KT; ++kt) {
        if (kt + 1 < KT) CP_WAIT(1); else CP_WAIT(0);
        __syncthreads();
        if (kt + 2 < KT) load_stage(kt + 2, (kt + 2) % 3);

        const uint32_t sA = sbase + (kt % 3) * TG_STAGE;
        const uint32_t sB = sA + 16384;

        #pragma unroll
        for (int ks = 0; ks < 4; ++ks) {
            uint32_t af[4][4];
            #pragma unroll
            for (int mt = 0; mt < 4; ++mt) {
                const int row = wm * 64 + mt * 16 + aRow;
                const uint32_t ad = sA + swz((uint32_t)(row * 128 + ks * 32 + aChk * 16));
                ldmx4(af[mt][0], af[mt][1], af[mt][2], af[mt][3], ad);
            }
            uint32_t bf[4][2];
            #pragma unroll
            for (int np = 0; np < 2; ++np) {
                const int nrow = wn * 32 + np * 16 + bRow;
                const uint32_t bd = sB + swz((uint32_t)(nrow * 128 + ks * 32 + bChk * 16));
                uint32_t t0, t1, t2, t3;
                ldmx4(t0, t1, t2, t3, bd);
                bf[np * 2][0] = t0;     bf[np * 2][1] = t1;
                bf[np * 2 + 1][0] = t2; bf[np * 2 + 1][1] = t3;
            }
            #pragma unroll
            for (int mt = 0; mt < 4; ++mt)
                #pragma unroll
                for (int nt = 0; nt < 4; ++nt)
                    mma_f16(acc[mt][nt][0], acc[mt][nt][1],
                            acc[mt][nt][2], acc[mt][nt][3],
                            af[mt][0], af[mt][1], af[mt][2], af[mt][3],
                            bf[nt][0], bf[nt][1]);
        }
    }

    #pragma unroll
    for (int mt = 0; mt < 4; mt++) {
        const int r0g = brow * 128 + wm * 64 + mt * 16 + g;
        const int r1g = r0g + 8;
        #pragma unroll
        for (int nt = 0; nt < 4; nt++) {
            const int c = bcol * 128 + wn * 32 + nt * 8 + tg * 2;
            float2 o0 = make_float2(acc[mt][nt][0], acc[mt][nt][1]);
            float2 o1 = make_float2(acc[mt][nt][2], acc[mt][nt][3]);
            if constexpr (EPI >= 1) {
                float2 bv = *reinterpret_cast<const float2*>(bias + c);
                o0.x += bv.x; o0.y += bv.y;
                o1.x += bv.x; o1.y += bv.y;
            }
            if constexpr (EPI == 1) {
                float2 rv0 = *reinterpret_cast<const float2*>(resid + (size_t)r0g * N + c);
                float2 rv1 = *reinterpret_cast<const float2*>(resid + (size_t)r1g * N + c);
                o0.x += rv0.x; o0.y += rv0.y;
                o1.x += rv1.x; o1.y += rv1.y;
                float* C = (float*)Cv;
                *reinterpret_cast<float2*>(C + (size_t)r0g * N + c) = o0;
                *reinterpret_cast<float2*>(C + (size_t)r1g * N + c) = o1;
            } else {
                if constexpr (EPI == 2) {
                    o0.x = fmaxf(o0.x, 0.f); o0.y = fmaxf(o0.y, 0.f);
                    o1.x = fmaxf(o1.x, 0.f); o1.y = fmaxf(o1.y, 0.f);
                }
                __half* C = (__half*)Cv;
                __half2 h0 = __floats2half2_rn(o0.x, o0.y);
                __half2 h1 = __floats2half2_rn(o1.x, o1.y);
                *reinterpret_cast<__half2*>(C + (size_t)r0g * N + c) = h0;
                *reinterpret_cast<__half2*>(C + (size_t)r1g * N + c) = h1;
            }
        }
    }
}

// ---------------- flash attention v9: in-kernel split-K merge ----------------
#define FA_SMEM (5 * 64 * 128)    // 40 KB

__global__ __launch_bounds__(128, 4) void flash_tc(
    const __half* __restrict__ qkv, __half* __restrict__ out,
    float* __restrict__ pO, float* __restrict__ pml, int* __restrict__ cnt)
{
    extern __shared__ char fsm[];
    __shared__ int s_old;
    const uint32_t qsb = smem_u32(fsm);
    const int tid  = threadIdx.x;
    const int warp = tid >> 5;
    const int lane = tid & 31;
    const int g    = lane >> 2;
    const int tg   = lane & 3;

    // ---- work-sorted block id -> (h, qb, seg) ----
    const int id = blockIdx.x;     // 0..767
    int qb, seg, h;
    if (id < 256) {
        h = id & 15; qb = 16 + (id >> 4); seg = 0;
    } else {
        const int id2 = id - 256;
        const int s = 16 - (id2 >> 5);
        const int j = id2 & 31;
        if (j < 16) { h = j;      qb = 15 + s; seg = 1; }
        else        { h = j - 16; qb = s - 1;  seg = 0; }
    }
    const int q0   = qb * 64;
    const int w16  = warp * 16;
    const int kt0  = seg * 16;
    const int kt1  = min(qb + 1, kt0 + 16);
    const bool full = (kt0 == 0) && (kt1 == qb + 1);

    const int aRow = (lane & 7) + ((lane >> 3) & 1) * 8;
    const int aChk = lane >> 4;
    const int bRow = (lane & 7) + (lane >> 4) * 8;
    const int bChk = (lane >> 3) & 1;
    const int vKeyLoc = ((lane >> 3) & 1) * 8 + (lane & 7);
    const int vL7  = lane & 7;
    const int vL16 = lane >> 4;

    const __half* qp = qkv + h * HSZ;
    const __half* kp = qkv + DD + h * HSZ;
    const __half* vp = qkv + 2 * DD + h * HSZ;

    auto load_kv = [&](int kt, int b) {
        const uint32_t kb = qsb + 8192 + b * 16384;
        const uint32_t vb = kb + 8192;
        #pragma unroll
        for (int j = 0; j < 4; ++j) {
            int idx = j * 128 + tid;
            int r = idx >> 3, ck = idx & 7;
            size_t gi = (size_t)(kt * 64 + r) * (3 * DD) + ck * 8;
            uint32_t off = swz((uint32_t)(r * 128 + ck * 16));
            cpasync16(kb + off, kp + gi);
            cpasync16(vb + off, vp + gi);
        }
        CP_COMMIT();
    };

    {   // Q tile
        #pragma unroll
        for (int j = 0; j < 4; ++j) {
            int idx = j * 128 + tid;
            int r = idx >> 3, ck = idx & 7;
            cpasync16(qsb + swz((uint32_t)(r * 128 + ck * 16)),
                      qp + (size_t)(q0 + r) * (3 * DD) + ck * 8);
        }
        CP_COMMIT();
    }
    load_kv(kt0, kt0 & 1);

    float O[8][4];
    #pragma unroll
    for (int nt = 0; nt < 8; nt++)
        #pragma unroll
        for (int i = 0; i < 4; i++) O[nt][i] = 0.f;
    float m0 = -1e30f, m1 = -1e30f, l0 = 0.f, l1 = 0.f;

    const int row0 = q0 + w16 + g;
    const int row1 = row0 + 8;
    const float SC = 0.18033688011112042f;   // (1/8) * log2(e)

    for (int kt = kt0; kt < kt1; ++kt) {
        const bool has_next = (kt + 1 < kt1);
        if (has_next) load_kv(kt + 1, (kt + 1) & 1);
        if (has_next) CP_WAIT(1); else CP_WAIT(0);
        __syncthreads();

        const uint32_t ksb = qsb + 8192 + (kt & 1) * 16384;
        const uint32_t vsb = ksb + 8192;

        // ---- S = Q K^T ----
        float s[8][4];
        #pragma unroll
        for (int nt = 0; nt < 8; nt++)
            #pragma unroll
            for (int i = 0; i < 4; i++) s[nt][i] = 0.f;

        #pragma unroll
        for (int kk = 0; kk < 4; ++kk) {
            uint32_t a0, a1, a2, a3;
            ldmx4(a0, a1, a2, a3,
                  qsb + swz((uint32_t)((w16 + aRow) * 128 + kk * 32 + aChk * 16)));
            uint32_t bf[8][2];
            #pragma unroll
            for (int n16 = 0; n16 < 4; ++n16) {
                uint32_t t0, t1, t2, t3;
                ldmx4(t0, t1, t2, t3,
                      ksb + swz((uint32_t)((n16 * 16 + bRow) * 128 + kk * 32 + bChk * 16)));
                bf[n16 * 2][0] = t0;     bf[n16 * 2][1] = t1;
                bf[n16 * 2 + 1][0] = t2; bf[n16 * 2 + 1][1] = t3;
            }
            #pragma unroll
            for (int nt = 0; nt < 8; ++nt)
                mma_f16(s[nt][0], s[nt][1], s[nt][2], s[nt][3],
                        a0, a1, a2, a3, bf[nt][0], bf[nt][1]);
        }

        // ---- causal mask: only the diagonal tile ----
        if (kt == qb) {
            #pragma unroll
            for (int nt = 0; nt < 8; ++nt) {
                int c0 = kt * 64 + nt * 8 + 2 * tg;
                if (c0     > row0) s[nt][0] = -1e30f;
                if (c0 + 1 > row0) s[nt][1] = -1e30f;
                if (c0     > row1) s[nt][2] = -1e30f;
                if (c0 + 1 > row1) s[nt][3] = -1e30f;
            }
        }

        // ---- raw-domain row max ----
        float mb0 = -1e30f, mb1 = -1e30f;
        #pragma unroll
        for (int nt = 0; nt < 8; ++nt) {
            mb0 = fmaxf(mb0, fmaxf(s[nt][0], s[nt][1]));
            mb1 = fmaxf(mb1, fmaxf(s[nt][2], s[nt][3]));
        }
        mb0 = fmaxf(mb0, __shfl_xor_sync(0xffffffffu, mb0, 1));
        mb0 = fmaxf(mb0, __shfl_xor_sync(0xffffffffu, mb0, 2));
        mb1 = fmaxf(mb1, __shfl_xor_sync(0xffffffffu, mb1, 1));
        mb1 = fmaxf(mb1, __shfl_xor_sync(0xffffffffu, mb1, 2));

        float mn0 = fmaxf(m0, mb0), mn1 = fmaxf(m1, mb1);
        float al0 = fexp2((m0 - mn0) * SC), al1 = fexp2((m1 - mn1) * SC);
        m0 = mn0; m1 = mn1;
        const float ms0 = mn0 * SC, ms1 = mn1 * SC;

        float rs0 = 0.f, rs1 = 0.f;
        #pragma unroll
        for (int nt = 0; nt < 8; ++nt) {
            float p0 = fexp2(fmaf(s[nt][0], SC, -ms0));
            float p1 = fexp2(fmaf(s[nt][1], SC, -ms0));
            float p2 = fexp2(fmaf(s[nt][2], SC, -ms1));
            float p3 = fexp2(fmaf(s[nt][3], SC, -ms1));
            rs0 += p0 + p1; rs1 += p2 + p3;
            s[nt][0] = p0; s[nt][1] = p1; s[nt][2] = p2; s[nt][3] = p3;
        }
        rs0 += __shfl_xor_sync(0xffffffffu, rs0, 1);
        rs0 += __shfl_xor_sync(0xffffffffu, rs0, 2);
        rs1 += __shfl_xor_sync(0xffffffffu, rs1, 1);
        rs1 += __shfl_xor_sync(0xffffffffu, rs1, 2);
        l0 = l0 * al0 + rs0;
        l1 = l1 * al1 + rs1;

        #pragma unroll
        for (int nt = 0; nt < 8; ++nt) {
            O[nt][0] *= al0; O[nt][1] *= al0;
            O[nt][2] *= al1; O[nt][3] *= al1;
        }

        // ---- O += P V ----
        #pragma unroll
        for (int kk = 0; kk < 4; ++kk) {
            uint32_t a0 = packh2(s[2*kk][0],   s[2*kk][1]);
            uint32_t a1 = packh2(s[2*kk][2],   s[2*kk][3]);
            uint32_t a2 = packh2(s[2*kk+1][0], s[2*kk+1][1]);
            uint32_t a3 = packh2(s[2*kk+1][2], s[2*kk+1][3]);
            #pragma unroll
            for (int i = 0; i < 4; ++i) {
                const int key = 16 * kk + vKeyLoc;
                const uint32_t dblk = (uint32_t)(((2 * i + vL16) ^ vL7) * 16);
                uint32_t t0, t1, t2, t3;
                ldmx4t(t0, t1, t2, t3, vsb + (uint32_t)(key * 128) + dblk);
                mma_f16(O[2*i][0], O[2*i][1], O[2*i][2], O[2*i][3],
                        a0, a1, a2, a3, t0, t1);
                mma_f16(O[2*i+1][0], O[2*i+1][1], O[2*i+1][2], O[2*i+1][3],
                        a0, a1, a2, a3, t2, t3);
            }
        }
        if (has_next) __syncthreads();
    }

    if (full) {
        float inv0 = 1.0f / l0, inv1 = 1.0f / l1;
        #pragma unroll
        for (int nt = 0; nt < 8; ++nt) {
            int c = h * HSZ + nt * 8 + 2 * tg;
            __half2 o0 = __floats2half2_rn(O[nt][0] * inv0, O[nt][1] * inv0);
            __half2 o1 = __floats2half2_rn(O[nt][2] * inv1, O[nt][3] * inv1);
            *reinterpret_cast<__half2*>(out + (size_t)row0 * DD + c) = o0;
            *reinterpret_cast<__half2*>(out + (size_t)row1 * DD + c) = o1;
        }
        return;
    }

    // ---- split-K: publish partials, ticket, loser exits / winner merges ----
    const int pair = h * 16 + (qb - 16);
    const int pme  = pair * 2 + seg;
    const int poth = pair * 2 + (1 - seg);
    {
        float* pb = pO + (size_t)pme * 4096;
        const int lr0 = w16 + g, lr1 = lr0 + 8;
        #pragma unroll
        for (int nt = 0; nt < 8; ++nt) {
            int c = nt * 8 + 2 * tg;
            *reinterpret_cast<float2*>(pb + lr0 * 64 + c) = make_float2(O[nt][0], O[nt][1]);
            *reinterpret_cast<float2*>(pb + lr1 * 64 + c) = make_float2(O[nt][2], O[nt][3]);
        }
        if (tg == 0) {
            float* mlb = pml + (size_t)pme * 128;
            mlb[lr0 * 2]     = m0;
            mlb[lr0 * 2 + 1] = l0;
            mlb[lr1 * 2]     = m1;
            mlb[lr1 * 2 + 1] = l1;
        }
    }
    __threadfence();
    __syncthreads();
    if (tid == 0) s_old = atomicAdd(&cnt[pair], 1);
    __syncthreads();
    if (s_old == 0) return;    // first to finish: peer will merge
    __threadfence();

    // second: merge my registers with peer's partials (fixed seg-order arithmetic)
    {
        const float* ob  = pO + (size_t)poth * 4096;
        const float* oml = pml + (size_t)poth * 128;
        const int lr0 = w16 + g, lr1 = lr0 + 8;
        float om0 = oml[lr0 * 2], ol0 = oml[lr0 * 2 + 1];
        float om1 = oml[lr1 * 2], ol1 = oml[lr1 * 2 + 1];
        float M0 = fmaxf(m0, om0), M1 = fmaxf(m1, om1);
        float wme0 = fexp2((m0 - M0) * SC), wot0 = fexp2((om0 - M0) * SC);
        float wme1 = fexp2((m1 - M1) * SC), wot1 = fexp2((om1 - M1) * SC);
        // A = seg0 operand, B = seg1 operand (order-invariant arithmetic)
        const bool iAmA = (seg == 0);
        float wA0 = iAmA ? wme0 : wot0, wB0 = iAmA ? wot0 : wme0;
        float wA1 = iAmA ? wme1 : wot1, wB1 = iAmA ? wot1 : wme1;
        float lA0 = iAmA ? l0 : ol0,    lB0 = iAmA ? ol0 : l0;
        float lA1 = iAmA ? l1 : ol1,    lB1 = iAmA ? ol1 : l1;
        float inv0 = 1.0f / fmaf(wB0, lB0, wA0 * lA0);
        float inv1 = 1.0f / fmaf(wB1, lB1, wA1 * lA1);
        #pragma unroll
        for (int nt = 0; nt < 8; ++nt) {
            int c = nt * 8 + 2 * tg;
            float2 q0v = *reinterpret_cast<const float2*>(ob + lr0 * 64 + c);
            float2 q1v = *reinterpret_cast<const float2*>(ob + lr1 * 64 + c);
            float A00 = iAmA ? O[nt][0] : q0v.x,  B00 = iAmA ? q0v.x : O[nt][0];
            float A01 = iAmA ? O[nt][1] : q0v.y,  B01 = iAmA ? q0v.y : O[nt][1];
            float A10 = iAmA ? O[nt][2] : q1v.x,  B10 = iAmA ? q1v.x : O[nt][2];
            float A11 = iAmA ? O[nt][3] : q1v.y,  B11 = iAmA ? q1v.y : O[nt][3];
            float r00 = fmaf(wB0, B00, wA0 * A00) * inv0;
            float r01 = fmaf(wB0, B01, wA0 * A01) * inv0;
            float r10 = fmaf(wB1, B10, wA1 * A10) * inv1;
            float r11 = fmaf(wB1, B11, wA1 * A11) * inv1;
            int gc = h * HSZ + c;
            *reinterpret_cast<__half2*>(out + (size_t)(q0 + lr0) * DD + gc) =
                __floats2half2_rn(r00, r01);
            *reinterpret_cast<__half2*>(out + (size_t)(q0 + lr1) * DD + gc) =
                __floats2half2_rn(r10, r11);
        }
    }
}

// ---------------- launch ----------------
extern "C" void kernel_launch(void* const* d_in, const int* in_sizes, int n_in,
                              void* d_out, int out_size)
{
    const float* x    = (const float*)d_in[0];
    const float* Wq   = (const float*)d_in[1];
    const float* Wk   = (const float*)d_in[2];
    const float* Wv   = (const float*)d_in[3];
    const float* Wo   = (const float*)d_in[4];
    const float* bo   = (const float*)d_in[5];
    const float* W1   = (const float*)d_in[6];
    const float* b1   = (const float*)d_in[7];
    const float* W2   = (const float*)d_in[8];
    const float* b2   = (const float*)d_in[9];
    const float* ln1s = (const float*)d_in[10];
    const float* ln1b = (const float*)d_in[11];
    const float* ln2s = (const float*)d_in[12];
    const float* ln2b = (const float*)d_in[13];
    float* out = (float*)d_out;

    __half *h, *wqkvT, *woT, *w1T, *w2T, *att, *ff, *qkv;
    float *x2, *pO, *pml;
    int *cnt;
    cudaGetSymbolAddress((void**)&h,     g_h);
    cudaGetSymbolAddress((void**)&wqkvT, g_wqkvT);
    cudaGetSymbolAddress((void**)&woT,   g_WoT);
    cudaGetSymbolAddress((void**)&w1T,   g_W1T);
    cudaGetSymbolAddress((void**)&w2T,   g_W2T);
    cudaGetSymbolAddress((void**)&qkv,   g_qkv);
    cudaGetSymbolAddress((void**)&att,   g_att);
    cudaGetSymbolAddress((void**)&x2,    g_x2);
    cudaGetSymbolAddress((void**)&ff,    g_ff);
    cudaGetSymbolAddress((void**)&pO,    g_pO);
    cudaGetSymbolAddress((void**)&pml,   g_pml);
    cudaGetSymbolAddress((void**)&cnt,   g_cnt);

    cudaFuncSetAttribute(flash_tc, cudaFuncAttributeMaxDynamicSharedMemorySize, FA_SMEM);
    cudaFuncSetAttribute(tg2<0>, cudaFuncAttributeMaxDynamicSharedMemorySize, TG_SMEM);
    cudaFuncSetAttribute(tg2<1>, cudaFuncAttributeMaxDynamicSharedMemorySize, TG_SMEM);
    cudaFuncSetAttribute(tg2<2>, cudaFuncAttributeMaxDynamicSharedMemorySize, TG_SMEM);

    // 1. prep: weight transposes + LN1 + ticket zeroing (one launch)
    prep_kernel<<<12288 + 2048 + 1, 256>>>(Wq, Wk, Wv, Wo, W1, W2,
                                           wqkvT, woT, w1T, w2T,
                                           x, ln1s, ln1b, h, cnt);
    // 2. QKV GEMM (fp16 out)
    tg2<0><<<dim3(3 * DD / 128, TT / 128), 256, TG_SMEM>>>(
        TT, 3 * DD, DD, h, wqkvT, nullptr, nullptr, qkv);
    // 3. flash attention split-K with in-kernel merge
    flash_tc<<<768, 128, FA_SMEM>>>(qkv, att, pO, pml, cnt);
    // 4. output proj + bias + residual (fp32 out)
    tg2<1><<<dim3(DD / 128, TT / 128), 256, TG_SMEM>>>(
        TT, DD, DD, att, woT, bo, x, x2);
    // 5. LN2 -> fp16
    ln_kernel<<<TT, 256>>>(x2, ln2s, ln2b, h);
    // 6. FFN1 (relu, fp16 out)
    tg2<2><<<dim3(DFF / 128, TT / 128), 256, TG_SMEM>>>(
        TT, DFF, DD, h, w1T, b1, nullptr, ff);
    // 7. FFN2 (fp32 out)
    tg2<1><<<dim3(DD / 128, TT / 128), 256, TG_SMEM>>>(
        TT, DD, DFF, ff, w2T, b2, x2, out);
}